// round 10
// baseline (speedup 1.0000x reference)
#include <cuda_runtime.h>
#include <cuda_bf16.h>
#include <cstdint>

#define BN 8192
#define CDIM 256
#define MT 64
#define NT 64
#define TTILES (BN / NT)   // 128
#define ITERS (TTILES / 2) // 64 iterations; each = one tile per key-group
#define ROWB 512           // smem bytes per tile row (256 bf16)

#define SQ_OFF 0
#define SK_OFF 32768               // 3 slots x 64KB (one tile-pair each)
#define PAIR_BYTES 65536
#define SMEM_TOTAL (32768 + 3 * PAIR_BYTES)   // 229376 <= 232448 max
// epilogue overlays (K region dead by then)
#define OFF_OX  32768              // O exchange: 64 x 256 f32 = 64KB
#define OFF_DN  (32768 + 65536)    // 64 f32 denominators

__device__ float         g_f32[BN * CDIM];   // normalized f (fp32, for blend)
__device__ __nv_bfloat16 g_fbf[BN * CDIM];   // normalized f (bf16, MMA operand)

// ---------------------------------------------------------------- helpers
__device__ __forceinline__ uint32_t smem_u32(const void* p) {
    uint32_t a;
    asm("{ .reg .u64 t; cvta.to.shared.u64 t, %1; cvt.u32.u64 %0, t; }" : "=r"(a) : "l"(p));
    return a;
}
__device__ __forceinline__ void cp16(uint32_t dst, const void* src) {
    asm volatile("cp.async.cg.shared.global [%0], [%1], 16;" :: "r"(dst), "l"(src));
}
#define CP_COMMIT() asm volatile("cp.async.commit_group;" ::: "memory")

__device__ __forceinline__ void ldsm4(uint32_t a, uint32_t& r0, uint32_t& r1,
                                      uint32_t& r2, uint32_t& r3) {
    asm volatile("ldmatrix.sync.aligned.m8n8.x4.shared.b16 {%0,%1,%2,%3}, [%4];"
                 : "=r"(r0), "=r"(r1), "=r"(r2), "=r"(r3) : "r"(a));
}
__device__ __forceinline__ void ldsm4t(uint32_t a, uint32_t& r0, uint32_t& r1,
                                       uint32_t& r2, uint32_t& r3) {
    asm volatile("ldmatrix.sync.aligned.m8n8.x4.trans.shared.b16 {%0,%1,%2,%3}, [%4];"
                 : "=r"(r0), "=r"(r1), "=r"(r2), "=r"(r3) : "r"(a));
}
__device__ __forceinline__ void mma16816(float (&c)[4], uint32_t a0, uint32_t a1,
                                         uint32_t a2, uint32_t a3,
                                         uint32_t b0, uint32_t b1) {
    asm volatile("mma.sync.aligned.m16n8k16.row.col.f32.bf16.bf16.f32 "
                 "{%0,%1,%2,%3}, {%4,%5,%6,%7}, {%8,%9}, {%0,%1,%2,%3};"
                 : "+f"(c[0]), "+f"(c[1]), "+f"(c[2]), "+f"(c[3])
                 : "r"(a0), "r"(a1), "r"(a2), "r"(a3), "r"(b0), "r"(b1));
}

// Load ROWS tile rows (256 bf16 each) into smem, 512B rows, XOR swizzle.
template <int ROWS>
__device__ __forceinline__ void load_rows(uint32_t dst, const __nv_bfloat16* src, int tid) {
#pragma unroll
    for (int q = 0; q < ROWS * 32 / 256; q++) {
        int i   = tid + q * 256;
        int row = i >> 5;
        int u   = i & 31;
        uint32_t d = dst + row * ROWB + ((u << 4) ^ ((row & 7) << 4));
        cp16(d, src + (size_t)row * CDIM + u * 8);
    }
}

// ---------------------------------------------------------------------------
// Kernel 1: row L2-normalize
// ---------------------------------------------------------------------------
__global__ void __launch_bounds__(256) norm_kernel(const float* __restrict__ in) {
    int row  = blockIdx.x * 8 + (threadIdx.x >> 5);
    int lane = threadIdx.x & 31;
    const float* r = in + (size_t)row * CDIM;
    float v[8]; float ss = 0.f;
#pragma unroll
    for (int i = 0; i < 8; i++) { v[i] = r[lane + 32 * i]; ss = fmaf(v[i], v[i], ss); }
#pragma unroll
    for (int o = 16; o > 0; o >>= 1) ss += __shfl_xor_sync(0xffffffffu, ss, o);
    float inv = 1.0f / fmaxf(sqrtf(ss), 1e-12f);
    float*         o32 = g_f32 + (size_t)row * CDIM;
    __nv_bfloat16* obf = g_fbf + (size_t)row * CDIM;
#pragma unroll
    for (int i = 0; i < 8; i++) {
        float x = v[i] * inv;
        o32[lane + 32 * i] = x;
        obf[lane + 32 * i] = __float2bfloat16(x);
    }
}

// ---------------------------------------------------------------------------
// Kernel 2: fused attention, 2 key-groups x 4 warps, software-pipelined:
// within each iteration the S(t+1) GEMM and the O(t) GEMM are interleaved in
// one straight-line region -> two independent ldsm/mma chains per warp.
// Scores in [-1,1] -> no softmax max tracking.
// ---------------------------------------------------------------------------
__global__ void __launch_bounds__(256, 1) attn_kernel(float* __restrict__ out) {
    extern __shared__ char smem[];
    const uint32_t sb = smem_u32(smem);
    const int tid  = threadIdx.x;
    const int lane = tid & 31;
    const int wid  = tid >> 5;
    const int wm   = wid & 3;     // warp-in-group: 16-row slice
    const int gg   = wid >> 2;    // key group 0/1
    const int g    = lane >> 2;
    const int tg   = lane & 3;
    const int qbase = blockIdx.x * MT;

    // prologue: Q + three tile-pairs
    load_rows<64>(sb + SQ_OFF, g_fbf + (size_t)qbase * CDIM, tid);
    load_rows<128>(sb + SK_OFF,                  g_fbf,                          tid); CP_COMMIT();
    load_rows<128>(sb + SK_OFF + PAIR_BYTES,     g_fbf + (size_t)128 * CDIM,     tid); CP_COMMIT();
    load_rows<128>(sb + SK_OFF + 2 * PAIR_BYTES, g_fbf + (size_t)256 * CDIM,     tid); CP_COMMIT();

    // per-thread ldmatrix address components
    const int rowA = wm * 16 + (lane & 15);
    const uint32_t aBase = sb + SQ_OFF + rowA * ROWB;
    const int chA = (lane >> 4) << 4, swzA = (rowA & 7) << 4;

    const int rowB0 = (lane & 7) + ((lane >> 4) << 3);
    const int chB = ((lane >> 3) & 1) << 4, swzB = (lane & 7) << 4;

    const int rowV0 = (lane & 7) + (((lane >> 3) & 1) << 3);
    const int chV = (lane >> 4) << 4, swzV = (lane & 7) << 4;

    float O[32][4];
#pragma unroll
    for (int j = 0; j < 32; j++) { O[j][0] = O[j][1] = O[j][2] = O[j][3] = 0.f; }
    float d0 = 0.f, d1 = 0.f;
    float S[8][4];

    // ---- prologue S(0): needs pair0 ----
    asm volatile("cp.async.wait_group 2;" ::: "memory");
    __syncthreads();
    {
        const uint32_t kS = sb + SK_OFF + (uint32_t)gg * 32768u;
#pragma unroll
        for (int j = 0; j < 8; j++) S[j][0] = S[j][1] = S[j][2] = S[j][3] = 0.f;
#pragma unroll
        for (int ks = 0; ks < 16; ks++) {
            uint32_t a0, a1, a2, a3;
            ldsm4(aBase + (uint32_t)((chA + 32 * ks) ^ swzA), a0, a1, a2, a3);
#pragma unroll
            for (int j = 0; j < 4; j++) {
                uint32_t b0, b1, b2, b3;
                ldsm4(kS + (rowB0 + 16 * j) * ROWB + (uint32_t)((chB + 32 * ks) ^ swzB),
                      b0, b1, b2, b3);
                mma16816(S[2 * j],     a0, a1, a2, a3, b0, b1);
                mma16816(S[2 * j + 1], a0, a1, a2, a3, b2, b3);
            }
        }
    }

#pragma unroll 1
    for (int it = 0; it < ITERS; it++) {
        // pair(it+1) resident (pair(it+2) may still be in flight)
        asm volatile("cp.async.wait_group 1;" ::: "memory");
        __syncthreads();

        // ---- P = exp(S(it)); denominators ----
        uint32_t P[4][4];
#pragma unroll
        for (int j = 0; j < 8; j++) {
            float e0 = __expf(S[j][0]), e1 = __expf(S[j][1]);
            float e2 = __expf(S[j][2]), e3 = __expf(S[j][3]);
            d0 += e0 + e1;  d1 += e2 + e3;
            uint32_t plo, phi;
            asm("cvt.rn.bf16x2.f32 %0, %1, %2;" : "=r"(plo) : "f"(e1), "f"(e0));
            asm("cvt.rn.bf16x2.f32 %0, %1, %2;" : "=r"(phi) : "f"(e3), "f"(e2));
            P[j >> 1][(j & 1) * 2 + 0] = plo;
            P[j >> 1][(j & 1) * 2 + 1] = phi;
        }

        // ---- fused: S(it+1) = Q@K(it+1)^T  interleaved with  O += P@V(it) ----
        // (at it==ITERS-1 the S part computes on stale-but-finite data; unused)
        float Sn[8][4];
#pragma unroll
        for (int j = 0; j < 8; j++) Sn[j][0] = Sn[j][1] = Sn[j][2] = Sn[j][3] = 0.f;
        const uint32_t kV = sb + SK_OFF + (uint32_t)(it % 3) * PAIR_BYTES
                               + (uint32_t)gg * 32768u;
        const uint32_t kS = sb + SK_OFF + (uint32_t)((it + 1) % 3) * PAIR_BYTES
                               + (uint32_t)gg * 32768u;
#pragma unroll
        for (int s = 0; s < 16; s++) {
            // S(it+1) step ks = s
            uint32_t a0, a1, a2, a3;
            ldsm4(aBase + (uint32_t)((chA + 32 * s) ^ swzA), a0, a1, a2, a3);
#pragma unroll
            for (int j = 0; j < 4; j++) {
                uint32_t b0, b1, b2, b3;
                ldsm4(kS + (rowB0 + 16 * j) * ROWB + (uint32_t)((chB + 32 * s) ^ swzB),
                      b0, b1, b2, b3);
                mma16816(Sn[2 * j],     a0, a1, a2, a3, b0, b1);
                mma16816(Sn[2 * j + 1], a0, a1, a2, a3, b2, b3);
            }
            // O(it) step: kb = s>>2, nq = (s&3)*4 .. +3
            const int kb = s >> 2;
            const uint32_t vrow = kV + (rowV0 + 16 * kb) * ROWB;
#pragma unroll
            for (int q = 0; q < 4; q++) {
                const int nq = (s & 3) * 4 + q;
                uint32_t b0, b1, b2, b3;
                ldsm4t(vrow + (uint32_t)((chV + 32 * nq) ^ swzV), b0, b1, b2, b3);
                mma16816(O[2 * nq],     P[kb][0], P[kb][1], P[kb][2], P[kb][3], b0, b1);
                mma16816(O[2 * nq + 1], P[kb][0], P[kb][1], P[kb][2], P[kb][3], b2, b3);
            }
        }
#pragma unroll
        for (int j = 0; j < 8; j++) {
            S[j][0] = Sn[j][0]; S[j][1] = Sn[j][1];
            S[j][2] = Sn[j][2]; S[j][3] = Sn[j][3];
        }

        __syncthreads();   // all warps done reading pair(it) before its slot refills
        if (it + 3 < ITERS) {
            load_rows<128>(sb + SK_OFF + (uint32_t)(it % 3) * PAIR_BYTES,
                           g_fbf + (size_t)(it + 3) * 128 * CDIM, tid);
            CP_COMMIT();
        }
    }

    // ---- denominators: reduce across the 4 threads sharing a row ----
#pragma unroll
    for (int off = 1; off <= 2; off <<= 1) {
        d0 += __shfl_xor_sync(0xffffffffu, d0, off);
        d1 += __shfl_xor_sync(0xffffffffu, d1, off);
    }

    // ---- combine the two key-groups' partials via smem ----
    float* sOX = (float*)(smem + OFF_OX);
    float* sDN = (float*)(smem + OFF_DN);
    const int r0l = wm * 16 + g;
    const int r1l = r0l + 8;

    if (gg == 1) {
#pragma unroll
        for (int j = 0; j < 32; j++) {
            int col = 8 * j + 2 * tg;
            *(float2*)(sOX + r0l * CDIM + col) = make_float2(O[j][0], O[j][1]);
            *(float2*)(sOX + r1l * CDIM + col) = make_float2(O[j][2], O[j][3]);
        }
        if (tg == 0) { sDN[r0l] = d0; sDN[r1l] = d1; }
    }
    __syncthreads();
    if (gg == 0) {
        const float invd0 = 0.2f / (d0 + sDN[r0l]);
        const float invd1 = 0.2f / (d1 + sDN[r1l]);
        const float* f0 = g_f32 + (size_t)(qbase + r0l) * CDIM;
        const float* f1 = g_f32 + (size_t)(qbase + r1l) * CDIM;
        float ss0 = 0.f, ss1 = 0.f;
#pragma unroll
        for (int j = 0; j < 32; j++) {
            int col = 8 * j + 2 * tg;
            float2 xa = *(const float2*)(sOX + r0l * CDIM + col);
            float2 xb = *(const float2*)(sOX + r1l * CDIM + col);
            float2 fa = *(const float2*)(f0 + col);
            float2 fb = *(const float2*)(f1 + col);
            O[j][0] = fmaf(0.8f, fa.x, invd0 * (O[j][0] + xa.x));
            O[j][1] = fmaf(0.8f, fa.y, invd0 * (O[j][1] + xa.y));
            O[j][2] = fmaf(0.8f, fb.x, invd1 * (O[j][2] + xb.x));
            O[j][3] = fmaf(0.8f, fb.y, invd1 * (O[j][3] + xb.y));
            ss0 = fmaf(O[j][0], O[j][0], fmaf(O[j][1], O[j][1], ss0));
            ss1 = fmaf(O[j][2], O[j][2], fmaf(O[j][3], O[j][3], ss1));
        }
#pragma unroll
        for (int off = 1; off <= 2; off <<= 1) {
            ss0 += __shfl_xor_sync(0xffffffffu, ss0, off);
            ss1 += __shfl_xor_sync(0xffffffffu, ss1, off);
        }
        const float inv0 = 1.0f / fmaxf(sqrtf(ss0), 1e-12f);
        const float inv1 = 1.0f / fmaxf(sqrtf(ss1), 1e-12f);
        float* o0 = out + (size_t)(qbase + r0l) * CDIM;
        float* o1 = out + (size_t)(qbase + r1l) * CDIM;
#pragma unroll
        for (int j = 0; j < 32; j++) {
            int col = 8 * j + 2 * tg;
            *(float2*)(o0 + col) = make_float2(O[j][0] * inv0, O[j][1] * inv0);
            *(float2*)(o1 + col) = make_float2(O[j][2] * inv1, O[j][3] * inv1);
        }
    }
}

// ---------------------------------------------------------------------------
extern "C" void kernel_launch(void* const* d_in, const int* in_sizes, int n_in,
                              void* d_out, int out_size) {
    const float* feats = (const float*)d_in[0];
    float*       out   = (float*)d_out;
    (void)in_sizes; (void)n_in; (void)out_size;

    cudaFuncSetAttribute(attn_kernel,
                         cudaFuncAttributeMaxDynamicSharedMemorySize, SMEM_TOTAL);

    norm_kernel<<<BN / 8, 256>>>(feats);
    attn_kernel<<<BN / MT, 256, SMEM_TOTAL>>>(out);
}

// round 11
// speedup vs baseline: 1.0961x; 1.0961x over previous
#include <cuda_runtime.h>
#include <cuda_fp16.h>
#include <cstdint>

#define BN 8192
#define CDIM 256
#define MT 64
#define NT 64
#define NTHREADS 384
#define NGROUPS 3
#define ITERS 43            // per-group tiles: 43,43,42 (group2 idle last iter)
#define ROWB 512            // smem bytes per tile row (256 f16)

#define SQ_OFF 0
#define SK_OFF 32768                 // 2 slabs x (3 groups x 32KB)
#define SLAB_BYTES (NGROUPS * 32768) // 98304
#define SMEM_TOTAL (32768 + 2 * SLAB_BYTES)   // 229376
// epilogue overlays (K region dead by then)
#define OFF_OX1 32768                // group1 partial O: 64x256 f32 = 64KB
#define OFF_OX2 (32768 + 65536)      // group2 partial O
#define OFF_DN1 (32768 + 2 * 65536)          // 64 f32
#define OFF_DN2 (32768 + 2 * 65536 + 256)    // 64 f32

__device__ float  g_f32[BN * CDIM];  // normalized f (fp32, blend)
__device__ __half g_fh[BN * CDIM];   // normalized f (f16, MMA operand)

__constant__ int c_gbase[NGROUPS] = {0, 43, 86};

// ---------------------------------------------------------------- helpers
__device__ __forceinline__ uint32_t smem_u32(const void* p) {
    uint32_t a;
    asm("{ .reg .u64 t; cvta.to.shared.u64 t, %1; cvt.u32.u64 %0, t; }" : "=r"(a) : "l"(p));
    return a;
}
__device__ __forceinline__ void cp16(uint32_t dst, const void* src) {
    asm volatile("cp.async.cg.shared.global [%0], [%1], 16;" :: "r"(dst), "l"(src));
}
#define CP_COMMIT() asm volatile("cp.async.commit_group;" ::: "memory")

__device__ __forceinline__ void ldsm4(uint32_t a, uint32_t& r0, uint32_t& r1,
                                      uint32_t& r2, uint32_t& r3) {
    asm volatile("ldmatrix.sync.aligned.m8n8.x4.shared.b16 {%0,%1,%2,%3}, [%4];"
                 : "=r"(r0), "=r"(r1), "=r"(r2), "=r"(r3) : "r"(a));
}
__device__ __forceinline__ void ldsm4t(uint32_t a, uint32_t& r0, uint32_t& r1,
                                       uint32_t& r2, uint32_t& r3) {
    asm volatile("ldmatrix.sync.aligned.m8n8.x4.trans.shared.b16 {%0,%1,%2,%3}, [%4];"
                 : "=r"(r0), "=r"(r1), "=r"(r2), "=r"(r3) : "r"(a));
}
// f16 accumulate: C/D = 2 x f16x2 regs
__device__ __forceinline__ void mmaH(uint32_t (&c)[2], uint32_t a0, uint32_t a1,
                                     uint32_t a2, uint32_t a3,
                                     uint32_t b0, uint32_t b1) {
    asm volatile("mma.sync.aligned.m16n8k16.row.col.f16.f16.f16.f16 "
                 "{%0,%1}, {%2,%3,%4,%5}, {%6,%7}, {%0,%1};"
                 : "+r"(c[0]), "+r"(c[1])
                 : "r"(a0), "r"(a1), "r"(a2), "r"(a3), "r"(b0), "r"(b1));
}

// ---------------------------------------------------------------------------
// Kernel 1: row L2-normalize
// ---------------------------------------------------------------------------
__global__ void __launch_bounds__(256) norm_kernel(const float* __restrict__ in) {
    int row  = blockIdx.x * 8 + (threadIdx.x >> 5);
    int lane = threadIdx.x & 31;
    const float* r = in + (size_t)row * CDIM;
    float v[8]; float ss = 0.f;
#pragma unroll
    for (int i = 0; i < 8; i++) { v[i] = r[lane + 32 * i]; ss = fmaf(v[i], v[i], ss); }
#pragma unroll
    for (int o = 16; o > 0; o >>= 1) ss += __shfl_xor_sync(0xffffffffu, ss, o);
    float inv = 1.0f / fmaxf(sqrtf(ss), 1e-12f);
    float*  o32 = g_f32 + (size_t)row * CDIM;
    __half* ofh = g_fh  + (size_t)row * CDIM;
#pragma unroll
    for (int i = 0; i < 8; i++) {
        float x = v[i] * inv;
        o32[lane + 32 * i] = x;
        ofh[lane + 32 * i] = __float2half(x);
    }
}

// Load one slab: 3 tiles (one per group), 384 threads (128 per tile).
__device__ __forceinline__ void load_slab(uint32_t slab, int it, int tid) {
    const int g    = tid >> 7;           // which group's tile
    const int t128 = tid & 127;
    int tile = c_gbase[g] + it;
    tile = tile > 127 ? 127 : tile;      // clamp (group2 last iter is masked)
    const __half* src = g_fh + (size_t)tile * NT * CDIM;
    const uint32_t dst = slab + (uint32_t)g * 32768u;
#pragma unroll
    for (int q = 0; q < 16; q++) {
        int i   = t128 + q * 128;
        int row = i >> 5;
        int u   = i & 31;
        cp16(dst + row * ROWB + ((u << 4) ^ ((row & 7) << 4)),
             src + (size_t)row * CDIM + u * 8);
    }
}

// ---------------------------------------------------------------------------
// Kernel 2: fused attention, f16 MMA pipeline, 12 warps = 3 key-groups x 4.
// Each warp: 16 query rows, O (16x256 f16) = 64 regs. Scores in [-1,1] ->
// no softmax max tracking. Partials of groups 1,2 combined via smem.
// ---------------------------------------------------------------------------
__global__ void __launch_bounds__(NTHREADS, 1) attn_kernel(float* __restrict__ out) {
    extern __shared__ char smem[];
    const uint32_t sb = smem_u32(smem);
    const int tid  = threadIdx.x;
    const int lane = tid & 31;
    const int wid  = tid >> 5;
    const int wm   = wid & 3;     // warp-in-group: 16-row slice
    const int gg   = wid >> 2;    // key group 0/1/2
    const int g    = lane >> 2;
    const int tg   = lane & 3;
    const int qbase = blockIdx.x * MT;

    // prologue: Q + two slabs
    for (int i = tid; i < 2048; i += NTHREADS) {
        int row = i >> 5, u = i & 31;
        cp16(sb + SQ_OFF + row * ROWB + ((u << 4) ^ ((row & 7) << 4)),
             g_fh + (size_t)(qbase + row) * CDIM + u * 8);
    }
    load_slab(sb + SK_OFF, 0, tid);              CP_COMMIT();
    load_slab(sb + SK_OFF + SLAB_BYTES, 1, tid); CP_COMMIT();

    // per-thread ldmatrix address components
    const int rowA = wm * 16 + (lane & 15);
    const uint32_t aBase = sb + SQ_OFF + rowA * ROWB;
    const int chA = (lane >> 4) << 4, swzA = (rowA & 7) << 4;

    const int rowB0 = (lane & 7) + ((lane >> 4) << 3);
    const int chB = ((lane >> 3) & 1) << 4, swzB = (lane & 7) << 4;

    const int rowV0 = (lane & 7) + (((lane >> 3) & 1) << 3);
    const int chV = (lane >> 4) << 4, swzV = (lane & 7) << 4;

    uint32_t O[32][2];
#pragma unroll
    for (int j = 0; j < 32; j++) { O[j][0] = 0u; O[j][1] = 0u; }
    float d0 = 0.f, d1 = 0.f;

#pragma unroll 1
    for (int it = 0; it < ITERS; it++) {
        if (it == ITERS - 1) asm volatile("cp.async.wait_group 0;" ::: "memory");
        else                 asm volatile("cp.async.wait_group 1;" ::: "memory");
        __syncthreads();
        const uint32_t kbuf = sb + SK_OFF + (uint32_t)(it & 1) * SLAB_BYTES
                                 + (uint32_t)gg * 32768u;

        // ---- S = Q @ K^T (16x64 per warp, f16 accum) ----
        uint32_t S[8][2];
#pragma unroll
        for (int j = 0; j < 8; j++) { S[j][0] = 0u; S[j][1] = 0u; }
#pragma unroll
        for (int ks = 0; ks < 16; ks++) {
            uint32_t a0, a1, a2, a3;
            ldsm4(aBase + (uint32_t)((chA + 32 * ks) ^ swzA), a0, a1, a2, a3);
#pragma unroll
            for (int j = 0; j < 4; j++) {
                uint32_t b0, b1, b2, b3;
                ldsm4(kbuf + (rowB0 + 16 * j) * ROWB + (uint32_t)((chB + 32 * ks) ^ swzB),
                      b0, b1, b2, b3);
                mmaH(S[2 * j],     a0, a1, a2, a3, b0, b1);
                mmaH(S[2 * j + 1], a0, a1, a2, a3, b2, b3);
            }
        }

        // ---- P = act * exp(S); denominators; P laid out as A-fragments ----
        const float act = (gg == 2 && it == ITERS - 1) ? 0.f : 1.f;
        uint32_t P[4][4];
#pragma unroll
        for (int j = 0; j < 8; j++) {
            float2 s0 = __half22float2(*(__half2*)&S[j][0]);   // row g
            float2 s1 = __half22float2(*(__half2*)&S[j][1]);   // row g+8
            float e0 = act * __expf(s0.x), e1 = act * __expf(s0.y);
            float e2 = act * __expf(s1.x), e3 = act * __expf(s1.y);
            d0 += e0 + e1;  d1 += e2 + e3;
            uint32_t plo, phi;
            asm("cvt.rn.f16x2.f32 %0, %1, %2;" : "=r"(plo) : "f"(e1), "f"(e0));
            asm("cvt.rn.f16x2.f32 %0, %1, %2;" : "=r"(phi) : "f"(e3), "f"(e2));
            P[j >> 1][(j & 1) * 2 + 0] = plo;   // (2j tile -> a0/a1, 2j+1 -> a2/a3)
            P[j >> 1][(j & 1) * 2 + 1] = phi;
        }

        // ---- O += P @ V (f16 accum; V = same K tile via ldmatrix.trans) ----
#pragma unroll
        for (int kb = 0; kb < 4; kb++) {
            const uint32_t vrow = kbuf + (rowV0 + 16 * kb) * ROWB;
#pragma unroll
            for (int nq = 0; nq < 16; nq++) {
                uint32_t b0, b1, b2, b3;
                ldsm4t(vrow + (uint32_t)((chV + 32 * nq) ^ swzV), b0, b1, b2, b3);
                mmaH(O[2 * nq],     P[kb][0], P[kb][1], P[kb][2], P[kb][3], b0, b1);
                mmaH(O[2 * nq + 1], P[kb][0], P[kb][1], P[kb][2], P[kb][3], b2, b3);
            }
        }

        __syncthreads();   // all readers done before slot refill
        if (it + 2 < ITERS) {
            load_slab(sb + SK_OFF + (uint32_t)(it & 1) * SLAB_BYTES, it + 2, tid);
            CP_COMMIT();
        }
    }

    // ---- denominators: reduce across the 4 threads sharing a row ----
#pragma unroll
    for (int off = 1; off <= 2; off <<= 1) {
        d0 += __shfl_xor_sync(0xffffffffu, d0, off);
        d1 += __shfl_xor_sync(0xffffffffu, d1, off);
    }

    // ---- combine group partials via smem (groups 1,2 publish; group 0 sums) ----
    float* sOX1 = (float*)(smem + OFF_OX1);
    float* sOX2 = (float*)(smem + OFF_OX2);
    float* sDN1 = (float*)(smem + OFF_DN1);
    float* sDN2 = (float*)(smem + OFF_DN2);
    const int r0l = wm * 16 + g;
    const int r1l = r0l + 8;

    __syncthreads();       // K region now dead; safe to overlay
    if (gg > 0) {
        float* sOX = (gg == 1) ? sOX1 : sOX2;
        float* sDN = (gg == 1) ? sDN1 : sDN2;
#pragma unroll
        for (int j = 0; j < 32; j++) {
            int col = 8 * j + 2 * tg;
            float2 x0 = __half22float2(*(__half2*)&O[j][0]);
            float2 x1 = __half22float2(*(__half2*)&O[j][1]);
            *(float2*)(sOX + r0l * CDIM + col) = x0;
            *(float2*)(sOX + r1l * CDIM + col) = x1;
        }
        if (tg == 0) { sDN[r0l] = d0; sDN[r1l] = d1; }
    }
    __syncthreads();
    if (gg == 0) {
        const float invd0 = 0.2f / (d0 + sDN1[r0l] + sDN2[r0l]);
        const float invd1 = 0.2f / (d1 + sDN1[r1l] + sDN2[r1l]);
        const float* f0 = g_f32 + (size_t)(qbase + r0l) * CDIM;
        const float* f1 = g_f32 + (size_t)(qbase + r1l) * CDIM;
        float acc0[64], acc1[64];
        float ss0 = 0.f, ss1 = 0.f;
#pragma unroll
        for (int j = 0; j < 32; j++) {
            int col = 8 * j + 2 * tg;
            float2 x0 = __half22float2(*(__half2*)&O[j][0]);
            float2 x1 = __half22float2(*(__half2*)&O[j][1]);
            float2 p1 = *(const float2*)(sOX1 + r0l * CDIM + col);
            float2 p2 = *(const float2*)(sOX2 + r0l * CDIM + col);
            float2 q1 = *(const float2*)(sOX1 + r1l * CDIM + col);
            float2 q2 = *(const float2*)(sOX2 + r1l * CDIM + col);
            float2 fa = *(const float2*)(f0 + col);
            float2 fb = *(const float2*)(f1 + col);
            float y0 = fmaf(0.8f, fa.x, invd0 * (x0.x + p1.x + p2.x));
            float y1 = fmaf(0.8f, fa.y, invd0 * (x0.y + p1.y + p2.y));
            float y2 = fmaf(0.8f, fb.x, invd1 * (x1.x + q1.x + q2.x));
            float y3 = fmaf(0.8f, fb.y, invd1 * (x1.y + q1.y + q2.y));
            acc0[2 * j] = y0; acc0[2 * j + 1] = y1;
            acc1[2 * j] = y2; acc1[2 * j + 1] = y3;
            ss0 = fmaf(y0, y0, fmaf(y1, y1, ss0));
            ss1 = fmaf(y2, y2, fmaf(y3, y3, ss1));
        }
#pragma unroll
        for (int off = 1; off <= 2; off <<= 1) {
            ss0 += __shfl_xor_sync(0xffffffffu, ss0, off);
            ss1 += __shfl_xor_sync(0xffffffffu, ss1, off);
        }
        const float inv0 = 1.0f / fmaxf(sqrtf(ss0), 1e-12f);
        const float inv1 = 1.0f / fmaxf(sqrtf(ss1), 1e-12f);
        float* o0 = out + (size_t)(qbase + r0l) * CDIM;
        float* o1 = out + (size_t)(qbase + r1l) * CDIM;
#pragma unroll
        for (int j = 0; j < 32; j++) {
            int col = 8 * j + 2 * tg;
            *(float2*)(o0 + col) = make_float2(acc0[2*j] * inv0, acc0[2*j+1] * inv0);
            *(float2*)(o1 + col) = make_float2(acc1[2*j] * inv1, acc1[2*j+1] * inv1);
        }
    }
}

// ---------------------------------------------------------------------------
extern "C" void kernel_launch(void* const* d_in, const int* in_sizes, int n_in,
                              void* d_out, int out_size) {
    const float* feats = (const float*)d_in[0];
    float*       out   = (float*)d_out;
    (void)in_sizes; (void)n_in; (void)out_size;

    cudaFuncSetAttribute(attn_kernel,
                         cudaFuncAttributeMaxDynamicSharedMemorySize, SMEM_TOTAL);

    norm_kernel<<<BN / 8, 256>>>(feats);
    attn_kernel<<<BN / MT, NTHREADS, SMEM_TOTAL>>>(out);
}

// round 12
// speedup vs baseline: 1.1769x; 1.0738x over previous
#include <cuda_runtime.h>
#include <cuda_fp16.h>
#include <cstdint>

#define BN 8192
#define CDIM 256
#define MT 64
#define NT 64
#define NTHREADS 384
#define ROWB 512            // smem bytes per tile row (256 f16)

#define SQ_OFF 0
#define SK_OFF 32768                 // per-group: 2 slots x 32KB at SK_OFF + gg*65536
#define SMEM_TOTAL (32768 + 3 * 65536)        // 229376
// epilogue overlays (K region dead by then)
#define OFF_OX1 32768
#define OFF_OX2 (32768 + 65536)
#define OFF_DN1 (32768 + 2 * 65536)
#define OFF_DN2 (32768 + 2 * 65536 + 256)

__device__ float  g_f32[BN * CDIM];  // normalized f (fp32, blend)
__device__ __half g_fh[BN * CDIM];   // normalized f (f16, MMA operand)

// ---------------------------------------------------------------- helpers
__device__ __forceinline__ uint32_t smem_u32(const void* p) {
    uint32_t a;
    asm("{ .reg .u64 t; cvta.to.shared.u64 t, %1; cvt.u32.u64 %0, t; }" : "=r"(a) : "l"(p));
    return a;
}
__device__ __forceinline__ void cp16(uint32_t dst, const void* src) {
    asm volatile("cp.async.cg.shared.global [%0], [%1], 16;" :: "r"(dst), "l"(src));
}
#define CP_COMMIT() asm volatile("cp.async.commit_group;" ::: "memory")

__device__ __forceinline__ void ldsm4(uint32_t a, uint32_t& r0, uint32_t& r1,
                                      uint32_t& r2, uint32_t& r3) {
    asm volatile("ldmatrix.sync.aligned.m8n8.x4.shared.b16 {%0,%1,%2,%3}, [%4];"
                 : "=r"(r0), "=r"(r1), "=r"(r2), "=r"(r3) : "r"(a));
}
__device__ __forceinline__ void ldsm4t(uint32_t a, uint32_t& r0, uint32_t& r1,
                                       uint32_t& r2, uint32_t& r3) {
    asm volatile("ldmatrix.sync.aligned.m8n8.x4.trans.shared.b16 {%0,%1,%2,%3}, [%4];"
                 : "=r"(r0), "=r"(r1), "=r"(r2), "=r"(r3) : "r"(a));
}
__device__ __forceinline__ void mmaH(uint32_t (&c)[2], uint32_t a0, uint32_t a1,
                                     uint32_t a2, uint32_t a3,
                                     uint32_t b0, uint32_t b1) {
    asm volatile("mma.sync.aligned.m16n8k16.row.col.f16.f16.f16.f16 "
                 "{%0,%1}, {%2,%3,%4,%5}, {%6,%7}, {%0,%1};"
                 : "+r"(c[0]), "+r"(c[1])
                 : "r"(a0), "r"(a1), "r"(a2), "r"(a3), "r"(b0), "r"(b1));
}
// p = ex2(s * log2e) on packed f16x2
__device__ __forceinline__ uint32_t exp_h2(uint32_t s) {
    uint32_t p;
    asm("{ .reg .b32 t;\n\t"
        "mul.rn.f16x2 t, %1, %2;\n\t"
        "ex2.approx.f16x2 %0, t; }"
        : "=r"(p) : "r"(s), "r"(0x3DC53DC5u));   // half2(1.4427, 1.4427)
    return p;
}

// ---------------------------------------------------------------------------
// Kernel 1: row L2-normalize
// ---------------------------------------------------------------------------
__global__ void __launch_bounds__(256) norm_kernel(const float* __restrict__ in) {
    int row  = blockIdx.x * 8 + (threadIdx.x >> 5);
    int lane = threadIdx.x & 31;
    const float* r = in + (size_t)row * CDIM;
    float v[8]; float ss = 0.f;
#pragma unroll
    for (int i = 0; i < 8; i++) { v[i] = r[lane + 32 * i]; ss = fmaf(v[i], v[i], ss); }
#pragma unroll
    for (int o = 16; o > 0; o >>= 1) ss += __shfl_xor_sync(0xffffffffu, ss, o);
    float inv = 1.0f / fmaxf(sqrtf(ss), 1e-12f);
    float*  o32 = g_f32 + (size_t)row * CDIM;
    __half* ofh = g_fh  + (size_t)row * CDIM;
#pragma unroll
    for (int i = 0; i < 8; i++) {
        float x = v[i] * inv;
        o32[lane + 32 * i] = x;
        ofh[lane + 32 * i] = __float2half(x);
    }
}

// Load one 64x256 f16 tile into a group buffer; called by the group's 128 threads.
__device__ __forceinline__ void load_tile_g(uint32_t dst, int tile, int t128) {
    const __half* src = g_fh + (size_t)tile * NT * CDIM;
#pragma unroll
    for (int q = 0; q < 16; q++) {
        int i   = t128 + q * 128;
        int row = i >> 5;
        int u   = i & 31;
        cp16(dst + row * ROWB + ((u << 4) ^ ((row & 7) << 4)),
             src + (size_t)row * CDIM + u * 8);
    }
}

// ---------------------------------------------------------------------------
// Kernel 2: fused attention, 12 warps = 3 DECOUPLED key-groups x 4 warps.
// Each group has its own double-buffered K tiles, its own cp.async stream and
// its own named barrier -> groups drift out of phase, hiding exp/phase bubbles.
// f16 MMA pipeline; scores in [-1,1] -> no softmax max tracking.
// ---------------------------------------------------------------------------
__global__ void __launch_bounds__(NTHREADS, 1) attn_kernel(float* __restrict__ out) {
    extern __shared__ char smem[];
    const uint32_t sb = smem_u32(smem);
    const int tid  = threadIdx.x;
    const int lane = tid & 31;
    const int wid  = tid >> 5;
    const int wm   = wid & 3;      // warp-in-group: 16-row slice
    const int gg   = wid >> 2;     // key group 0/1/2
    const int t128 = tid & 127;
    const int g    = lane >> 2;
    const int tg   = lane & 3;
    const int qbase = blockIdx.x * MT;

    const int GBASE = (gg == 0) ? 0 : (gg == 1 ? 43 : 86);
    const int NITER = (gg == 2) ? 42 : 43;
    const uint32_t kbase = sb + SK_OFF + (uint32_t)gg * 65536u;

    // prologue: Q (all threads) + this group's first two tiles
    for (int i = tid; i < 2048; i += NTHREADS) {
        int row = i >> 5, u = i & 31;
        cp16(sb + SQ_OFF + row * ROWB + ((u << 4) ^ ((row & 7) << 4)),
             g_fh + (size_t)(qbase + row) * CDIM + u * 8);
    }
    load_tile_g(kbase,          GBASE,     t128);  CP_COMMIT();   // c0 = Q-part + tile0
    load_tile_g(kbase + 32768u, GBASE + 1, t128);  CP_COMMIT();   // c1 = tile1
    asm volatile("cp.async.wait_group 1;" ::: "memory");          // c0 done
    __syncthreads();                                              // Q + all tile0s visible

    // per-thread ldmatrix address components
    const int rowA = wm * 16 + (lane & 15);
    const uint32_t aBase = sb + SQ_OFF + rowA * ROWB;
    const int chA = (lane >> 4) << 4, swzA = (rowA & 7) << 4;

    const int rowB0 = (lane & 7) + ((lane >> 4) << 3);
    const int chB = ((lane >> 3) & 1) << 4, swzB = (lane & 7) << 4;

    const int rowV0 = (lane & 7) + (((lane >> 3) & 1) << 3);
    const int chV = (lane >> 4) << 4, swzV = (lane & 7) << 4;

    uint32_t O[32][2];
#pragma unroll
    for (int j = 0; j < 32; j++) { O[j][0] = 0u; O[j][1] = 0u; }
    float d0 = 0.f, d1 = 0.f;

#pragma unroll 1
    for (int it = 0; it < NITER; it++) {
        if (it > 0) {
            if (it == NITER - 1) asm volatile("cp.async.wait_group 0;" ::: "memory");
            else                 asm volatile("cp.async.wait_group 1;" ::: "memory");
            asm volatile("bar.sync %0, 128;" :: "r"(gg + 1) : "memory");
        }
        const uint32_t kbuf = kbase + (uint32_t)(it & 1) * 32768u;

        // ---- S = Q @ K^T (16x64 per warp, f16 accum) ----
        uint32_t S[8][2];
#pragma unroll
        for (int j = 0; j < 8; j++) { S[j][0] = 0u; S[j][1] = 0u; }
#pragma unroll
        for (int ks = 0; ks < 16; ks++) {
            uint32_t a0, a1, a2, a3;
            ldsm4(aBase + (uint32_t)((chA + 32 * ks) ^ swzA), a0, a1, a2, a3);
#pragma unroll
            for (int j = 0; j < 4; j++) {
                uint32_t b0, b1, b2, b3;
                ldsm4(kbuf + (rowB0 + 16 * j) * ROWB + (uint32_t)((chB + 32 * ks) ^ swzB),
                      b0, b1, b2, b3);
                mmaH(S[2 * j],     a0, a1, a2, a3, b0, b1);
                mmaH(S[2 * j + 1], a0, a1, a2, a3, b2, b3);
            }
        }

        // ---- P = exp(S) via f16x2 ex2; denominators via HADD2 tree ----
        uint32_t P[4][4];
        __half2 sl = __float2half2_rn(0.f), sh = __float2half2_rn(0.f);
#pragma unroll
        for (int j = 0; j < 8; j++) {
            uint32_t plo = exp_h2(S[j][0]);
            uint32_t phi = exp_h2(S[j][1]);
            sl = __hadd2(sl, *(__half2*)&plo);
            sh = __hadd2(sh, *(__half2*)&phi);
            P[j >> 1][(j & 1) * 2 + 0] = plo;
            P[j >> 1][(j & 1) * 2 + 1] = phi;
        }
        { float2 a = __half22float2(sl); d0 += a.x + a.y; }
        { float2 b = __half22float2(sh); d1 += b.x + b.y; }

        // ---- O += P @ V (f16 accum; V = same K tile via ldmatrix.trans) ----
#pragma unroll
        for (int kb = 0; kb < 4; kb++) {
            const uint32_t vrow = kbuf + (rowV0 + 16 * kb) * ROWB;
#pragma unroll
            for (int nq = 0; nq < 16; nq++) {
                uint32_t b0, b1, b2, b3;
                ldsm4t(vrow + (uint32_t)((chV + 32 * nq) ^ swzV), b0, b1, b2, b3);
                mmaH(O[2 * nq],     P[kb][0], P[kb][1], P[kb][2], P[kb][3], b0, b1);
                mmaH(O[2 * nq + 1], P[kb][0], P[kb][1], P[kb][2], P[kb][3], b2, b3);
            }
        }

        asm volatile("bar.sync %0, 128;" :: "r"(gg + 1) : "memory");  // group done reading
        if (it + 2 < NITER) {
            load_tile_g(kbase + (uint32_t)(it & 1) * 32768u, GBASE + it + 2, t128);
            CP_COMMIT();
        }
    }

    // ---- denominators: reduce across the 4 threads sharing a row ----
#pragma unroll
    for (int off = 1; off <= 2; off <<= 1) {
        d0 += __shfl_xor_sync(0xffffffffu, d0, off);
        d1 += __shfl_xor_sync(0xffffffffu, d1, off);
    }

    // ---- combine group partials (groups 1,2 publish; group 0 sums) ----
    float* sOX1 = (float*)(smem + OFF_OX1);
    float* sOX2 = (float*)(smem + OFF_OX2);
    float* sDN1 = (float*)(smem + OFF_DN1);
    float* sDN2 = (float*)(smem + OFF_DN2);
    const int r0l = wm * 16 + g;
    const int r1l = r0l + 8;

    __syncthreads();       // all groups finished; K region dead, safe to overlay
    if (gg > 0) {
        float* sOX = (gg == 1) ? sOX1 : sOX2;
        float* sDN = (gg == 1) ? sDN1 : sDN2;
#pragma unroll
        for (int j = 0; j < 32; j++) {
            int col = 8 * j + 2 * tg;
            *(float2*)(sOX + r0l * CDIM + col) = __half22float2(*(__half2*)&O[j][0]);
            *(float2*)(sOX + r1l * CDIM + col) = __half22float2(*(__half2*)&O[j][1]);
        }
        if (tg == 0) { sDN[r0l] = d0; sDN[r1l] = d1; }
    }
    __syncthreads();
    if (gg == 0) {
        const float invd0 = 0.2f / (d0 + sDN1[r0l] + sDN2[r0l]);
        const float invd1 = 0.2f / (d1 + sDN1[r1l] + sDN2[r1l]);
        const float* f0 = g_f32 + (size_t)(qbase + r0l) * CDIM;
        const float* f1 = g_f32 + (size_t)(qbase + r1l) * CDIM;
        float acc0[64], acc1[64];
        float ss0 = 0.f, ss1 = 0.f;
#pragma unroll
        for (int j = 0; j < 32; j++) {
            int col = 8 * j + 2 * tg;
            float2 x0 = __half22float2(*(__half2*)&O[j][0]);
            float2 x1 = __half22float2(*(__half2*)&O[j][1]);
            float2 p1 = *(const float2*)(sOX1 + r0l * CDIM + col);
            float2 p2 = *(const float2*)(sOX2 + r0l * CDIM + col);
            float2 q1 = *(const float2*)(sOX1 + r1l * CDIM + col);
            float2 q2 = *(const float2*)(sOX2 + r1l * CDIM + col);
            float2 fa = *(const float2*)(f0 + col);
            float2 fb = *(const float2*)(f1 + col);
            float y0 = fmaf(0.8f, fa.x, invd0 * (x0.x + p1.x + p2.x));
            float y1 = fmaf(0.8f, fa.y, invd0 * (x0.y + p1.y + p2.y));
            float y2 = fmaf(0.8f, fb.x, invd1 * (x1.x + q1.x + q2.x));
            float y3 = fmaf(0.8f, fb.y, invd1 * (x1.y + q1.y + q2.y));
            acc0[2 * j] = y0; acc0[2 * j + 1] = y1;
            acc1[2 * j] = y2; acc1[2 * j + 1] = y3;
            ss0 = fmaf(y0, y0, fmaf(y1, y1, ss0));
            ss1 = fmaf(y2, y2, fmaf(y3, y3, ss1));
        }
#pragma unroll
        for (int off = 1; off <= 2; off <<= 1) {
            ss0 += __shfl_xor_sync(0xffffffffu, ss0, off);
            ss1 += __shfl_xor_sync(0xffffffffu, ss1, off);
        }
        const float inv0 = 1.0f / fmaxf(sqrtf(ss0), 1e-12f);
        const float inv1 = 1.0f / fmaxf(sqrtf(ss1), 1e-12f);
        float* o0 = out + (size_t)(qbase + r0l) * CDIM;
        float* o1 = out + (size_t)(qbase + r1l) * CDIM;
#pragma unroll
        for (int j = 0; j < 32; j++) {
            int col = 8 * j + 2 * tg;
            *(float2*)(o0 + col) = make_float2(acc0[2*j] * inv0, acc0[2*j+1] * inv0);
            *(float2*)(o1 + col) = make_float2(acc1[2*j] * inv1, acc1[2*j+1] * inv1);
        }
    }
}

// ---------------------------------------------------------------------------
extern "C" void kernel_launch(void* const* d_in, const int* in_sizes, int n_in,
                              void* d_out, int out_size) {
    const float* feats = (const float*)d_in[0];
    float*       out   = (float*)d_out;
    (void)in_sizes; (void)n_in; (void)out_size;

    cudaFuncSetAttribute(attn_kernel,
                         cudaFuncAttributeMaxDynamicSharedMemorySize, SMEM_TOTAL);

    norm_kernel<<<BN / 8, 256>>>(feats);
    attn_kernel<<<BN / MT, NTHREADS, SMEM_TOTAL>>>(out);
}

// round 13
// speedup vs baseline: 1.1889x; 1.0101x over previous
#include <cuda_runtime.h>
#include <cuda_fp16.h>
#include <cstdint>

#define BN 8192
#define CDIM 256
#define MT 64
#define NT 64
#define NTHREADS 384
#define ROWB 512            // smem bytes per K/Q tile row (256 f16)

#define SQ_OFF 0                      // Q: 64 x 512B = 32KB
#define SK_OFF 32768                  // K: 3 groups x 32KB (single-buffered)
#define SP_OFF 131072                 // P: 3 groups x 8KB (64 x 128B)
#define SMEM_TOTAL 155648
#define OFF_DN 65536                  // epilogue denom overlay (3 x 64 f32)

__device__ float  g_f32[BN * CDIM];   // normalized f (fp32, blend)
__device__ __half g_fh[BN * CDIM];    // normalized f (f16, MMA operand)

// ---------------------------------------------------------------- helpers
__device__ __forceinline__ uint32_t smem_u32(const void* p) {
    uint32_t a;
    asm("{ .reg .u64 t; cvta.to.shared.u64 t, %1; cvt.u32.u64 %0, t; }" : "=r"(a) : "l"(p));
    return a;
}
__device__ __forceinline__ void cp16(uint32_t dst, const void* src) {
    asm volatile("cp.async.cg.shared.global [%0], [%1], 16;" :: "r"(dst), "l"(src));
}
#define CP_COMMIT() asm volatile("cp.async.commit_group;" ::: "memory")

__device__ __forceinline__ void ldsm4(uint32_t a, uint32_t& r0, uint32_t& r1,
                                      uint32_t& r2, uint32_t& r3) {
    asm volatile("ldmatrix.sync.aligned.m8n8.x4.shared.b16 {%0,%1,%2,%3}, [%4];"
                 : "=r"(r0), "=r"(r1), "=r"(r2), "=r"(r3) : "r"(a));
}
__device__ __forceinline__ void ldsm4t(uint32_t a, uint32_t& r0, uint32_t& r1,
                                       uint32_t& r2, uint32_t& r3) {
    asm volatile("ldmatrix.sync.aligned.m8n8.x4.trans.shared.b16 {%0,%1,%2,%3}, [%4];"
                 : "=r"(r0), "=r"(r1), "=r"(r2), "=r"(r3) : "r"(a));
}
__device__ __forceinline__ void mmaH(uint32_t (&c)[2], uint32_t a0, uint32_t a1,
                                     uint32_t a2, uint32_t a3,
                                     uint32_t b0, uint32_t b1) {
    asm volatile("mma.sync.aligned.m16n8k16.row.col.f16.f16.f16.f16 "
                 "{%0,%1}, {%2,%3,%4,%5}, {%6,%7}, {%0,%1};"
                 : "+r"(c[0]), "+r"(c[1])
                 : "r"(a0), "r"(a1), "r"(a2), "r"(a3), "r"(b0), "r"(b1));
}
__device__ __forceinline__ uint32_t exp_h2(uint32_t s) {   // ex2(s*log2e), f16x2
    uint32_t p;
    asm("{ .reg .b32 t;\n\t"
        "mul.rn.f16x2 t, %1, %2;\n\t"
        "ex2.approx.f16x2 %0, t; }"
        : "=r"(p) : "r"(s), "r"(0x3DC53DC5u));
    return p;
}
// swizzled byte address inside the 64x256 f32 epilogue accumulator (1024B rows)
__device__ __forceinline__ int oacc_addr(int row, int cb) {
    return row * 1024 + ((((cb >> 4) ^ (row & 7)) << 4) | (cb & 15));
}

// ---------------------------------------------------------------------------
// Kernel 1: row L2-normalize
// ---------------------------------------------------------------------------
__global__ void __launch_bounds__(256) norm_kernel(const float* __restrict__ in) {
    int row  = blockIdx.x * 8 + (threadIdx.x >> 5);
    int lane = threadIdx.x & 31;
    const float* r = in + (size_t)row * CDIM;
    float v[8]; float ss = 0.f;
#pragma unroll
    for (int i = 0; i < 8; i++) { v[i] = r[lane + 32 * i]; ss = fmaf(v[i], v[i], ss); }
#pragma unroll
    for (int o = 16; o > 0; o >>= 1) ss += __shfl_xor_sync(0xffffffffu, ss, o);
    float inv = 1.0f / fmaxf(sqrtf(ss), 1e-12f);
    float*  o32 = g_f32 + (size_t)row * CDIM;
    __half* ofh = g_fh  + (size_t)row * CDIM;
#pragma unroll
    for (int i = 0; i < 8; i++) {
        float x = v[i] * inv;
        o32[lane + 32 * i] = x;
        ofh[lane + 32 * i] = __float2half(x);
    }
}

// Load one 64x256 f16 tile; called by the group's 128 threads.
__device__ __forceinline__ void load_tile_g(uint32_t dst, int tile, int t128) {
    const __half* src = g_fh + (size_t)tile * NT * CDIM;
#pragma unroll
    for (int q = 0; q < 16; q++) {
        int i   = t128 + q * 128;
        int row = i >> 5;
        int u   = i & 31;
        cp16(dst + row * ROWB + ((u << 4) ^ ((row & 7) << 4)),
             src + (size_t)row * CDIM + u * 8);
    }
}

// ---------------------------------------------------------------------------
// Kernel 2: 3 decoupled key-groups x 4 warps. S m-split (warp = 16 q-rows),
// O n-split (warp = 64 cols of all 64 rows) via P smem exchange -> V loads
// drop 4x. f16 MMA; scores in [-1,1] -> no softmax max tracking.
// ---------------------------------------------------------------------------
__global__ void __launch_bounds__(NTHREADS, 1) attn_kernel(float* __restrict__ out) {
    extern __shared__ char smem[];
    const uint32_t sb = smem_u32(smem);
    const int tid  = threadIdx.x;
    const int lane = tid & 31;
    const int wid  = tid >> 5;
    const int wm   = wid & 3;      // warp-in-group
    const int gg   = wid >> 2;     // key group 0/1/2
    const int t128 = tid & 127;
    const int g    = lane >> 2;
    const int tg   = lane & 3;
    const int qbase = blockIdx.x * MT;

    const int GBASE = (gg == 0) ? 0 : (gg == 1 ? 43 : 86);
    const int NITER = (gg == 2) ? 42 : 43;
    const uint32_t kbase = sb + SK_OFF + (uint32_t)gg * 32768u;
    const uint32_t pbase = sb + SP_OFF + (uint32_t)gg * 8192u;
    char* const pbytes   = smem + SP_OFF + gg * 8192;

    // prologue: Q (all threads) + this group's first tile
    for (int i = tid; i < 2048; i += NTHREADS) {
        int row = i >> 5, u = i & 31;
        cp16(sb + SQ_OFF + row * ROWB + ((u << 4) ^ ((row & 7) << 4)),
             g_fh + (size_t)(qbase + row) * CDIM + u * 8);
    }
    load_tile_g(kbase, GBASE, t128);
    CP_COMMIT();
    asm volatile("cp.async.wait_group 0;" ::: "memory");
    __syncthreads();

    // ldmatrix address components
    const int rowA = wm * 16 + (lane & 15);                 // S-phase A (Q rows)
    const uint32_t aBase = sb + SQ_OFF + rowA * ROWB;
    const int chA = (lane >> 4) << 4, swzA = (rowA & 7) << 4;

    const int rowB0 = (lane & 7) + ((lane >> 4) << 3);      // S-phase B (keys)
    const int chB = ((lane >> 3) & 1) << 4, swzB = (lane & 7) << 4;

    const int rowV0 = (lane & 7) + (((lane >> 3) & 1) << 3); // O-phase B (V, trans)
    const int chV = (lane >> 4) << 4, swzV = (lane & 7) << 4;

    const int rowPA = lane & 15;                             // O-phase A (P tile)
    const uint32_t pldBase = pbase + rowPA * 128;
    const int chP = (lane >> 4) << 4, swzP = (rowPA & 7) << 4;

    uint32_t O[4][8][2];
#pragma unroll
    for (int mb = 0; mb < 4; mb++)
#pragma unroll
        for (int nb = 0; nb < 8; nb++) { O[mb][nb][0] = 0u; O[mb][nb][1] = 0u; }
    float d0 = 0.f, d1 = 0.f;

#pragma unroll 1
    for (int it = 0; it < NITER; it++) {
        if (it > 0) {
            asm volatile("cp.async.wait_group 0;" ::: "memory");
            asm volatile("bar.sync %0, 128;" :: "r"(gg + 1) : "memory");  // K(it) visible
        }

        // ---- S = Q @ K^T (16 rows x 64 keys per warp, f16 accum) ----
        uint32_t S[8][2];
#pragma unroll
        for (int j = 0; j < 8; j++) { S[j][0] = 0u; S[j][1] = 0u; }
#pragma unroll
        for (int ks = 0; ks < 16; ks++) {
            uint32_t a0, a1, a2, a3;
            ldsm4(aBase + (uint32_t)((chA + 32 * ks) ^ swzA), a0, a1, a2, a3);
#pragma unroll
            for (int j = 0; j < 4; j++) {
                uint32_t b0, b1, b2, b3;
                ldsm4(kbase + (rowB0 + 16 * j) * ROWB + (uint32_t)((chB + 32 * ks) ^ swzB),
                      b0, b1, b2, b3);
                mmaH(S[2 * j],     a0, a1, a2, a3, b0, b1);
                mmaH(S[2 * j + 1], a0, a1, a2, a3, b2, b3);
            }
        }

        // ---- P = exp(S); denominators; store P slice to group smem tile ----
        {
            __half2 sl = __float2half2_rn(0.f), sh = __float2half2_rn(0.f);
            char* prow = pbytes + (wm * 16 + g) * 128 + 4 * tg;
#pragma unroll
            for (int kb = 0; kb < 4; kb++) {
                uint32_t p0 = exp_h2(S[2 * kb][0]);      // (row g,   keys 16kb+2tg)
                uint32_t p1 = exp_h2(S[2 * kb][1]);      // (row g+8, keys 16kb+2tg)
                uint32_t p2 = exp_h2(S[2 * kb + 1][0]);  // (row g,   keys 16kb+8+2tg)
                uint32_t p3 = exp_h2(S[2 * kb + 1][1]);  // (row g+8, ...)
                sl = __hadd2(sl, __hadd2(*(__half2*)&p0, *(__half2*)&p2));
                sh = __hadd2(sh, __hadd2(*(__half2*)&p1, *(__half2*)&p3));
                const int u0 = ((2 * kb) ^ g) << 4;
                const int u1 = ((2 * kb + 1) ^ g) << 4;
                *(uint32_t*)(prow + u0)        = p0;
                *(uint32_t*)(prow + 1024 + u0) = p1;     // +8 rows
                *(uint32_t*)(prow + u1)        = p2;
                *(uint32_t*)(prow + 1024 + u1) = p3;
            }
            float2 a = __half22float2(sl); d0 += a.x + a.y;
            float2 b = __half22float2(sh); d1 += b.x + b.y;
        }
        asm volatile("bar.sync %0, 128;" :: "r"(gg + 1) : "memory");  // P visible

        // ---- O += P @ V : n-split, warp owns cols 64*wm for all 64 rows ----
#pragma unroll
        for (int ks = 0; ks < 4; ks++) {
            uint32_t pa[4][4];
#pragma unroll
            for (int mb = 0; mb < 4; mb++)
                ldsm4(pldBase + mb * 2048 + (uint32_t)((32 * ks + chP) ^ swzP),
                      pa[mb][0], pa[mb][1], pa[mb][2], pa[mb][3]);
            const uint32_t vrow = kbase + (rowV0 + 16 * ks) * ROWB;
#pragma unroll
            for (int nq = 0; nq < 4; nq++) {
                uint32_t b0, b1, b2, b3;
                ldsm4t(vrow + (uint32_t)((128 * wm + 32 * nq + chV) ^ swzV),
                       b0, b1, b2, b3);
#pragma unroll
                for (int mb = 0; mb < 4; mb++) {
                    mmaH(O[mb][2 * nq],     pa[mb][0], pa[mb][1], pa[mb][2], pa[mb][3], b0, b1);
                    mmaH(O[mb][2 * nq + 1], pa[mb][0], pa[mb][1], pa[mb][2], pa[mb][3], b2, b3);
                }
            }
        }

        asm volatile("bar.sync %0, 128;" :: "r"(gg + 1) : "memory");  // K,P reads done
        if (it + 1 < NITER) {
            load_tile_g(kbase, GBASE + it + 1, t128);
            CP_COMMIT();
        }
    }

    // ---- denominators: quad reduce (rows fully owned per warp per group) ----
#pragma unroll
    for (int off = 1; off <= 2; off <<= 1) {
        d0 += __shfl_xor_sync(0xffffffffu, d0, off);
        d1 += __shfl_xor_sync(0xffffffffu, d1, off);
    }

    // ---- epilogue: sum the 3 group O partials into a 64x256 f32 smem tile ----
    __syncthreads();                       // all mainloops done; Q/K/P dead
    float* sDN = (float*)(smem + OFF_DN);
    if (tg == 0) {
        sDN[gg * 64 + wm * 16 + g]     = d0;
        sDN[gg * 64 + wm * 16 + g + 8] = d1;
    }
    if (gg == 0) {
#pragma unroll
        for (int mb = 0; mb < 4; mb++)
#pragma unroll
            for (int nb = 0; nb < 8; nb++) {
                int row = 16 * mb + g;
                int cb  = wm * 256 + nb * 32 + tg * 8;
                *(float2*)(smem + oacc_addr(row, cb))     = __half22float2(*(__half2*)&O[mb][nb][0]);
                *(float2*)(smem + oacc_addr(row + 8, cb)) = __half22float2(*(__half2*)&O[mb][nb][1]);
            }
    }
    __syncthreads();
#pragma unroll 1
    for (int turn = 1; turn <= 2; turn++) {
        if (gg == turn) {
#pragma unroll
            for (int mb = 0; mb < 4; mb++)
#pragma unroll
                for (int nb = 0; nb < 8; nb++) {
                    int row = 16 * mb + g;
                    int cb  = wm * 256 + nb * 32 + tg * 8;
                    float2* a0 = (float2*)(smem + oacc_addr(row, cb));
                    float2* a1 = (float2*)(smem + oacc_addr(row + 8, cb));
                    float2 v0 = __half22float2(*(__half2*)&O[mb][nb][0]);
                    float2 v1 = __half22float2(*(__half2*)&O[mb][nb][1]);
                    float2 c0 = *a0, c1 = *a1;
                    a0->x = c0.x + v0.x; a0->y = c0.y + v0.y;
                    a1->x = c1.x + v1.x; a1->y = c1.y + v1.y;
                }
        }
        __syncthreads();
    }

    // ---- final: blend with f, renormalize rows, write out ----
#pragma unroll 1
    for (int r = wid; r < MT; r += 12) {
        float dsum = sDN[r] + sDN[64 + r] + sDN[128 + r];
        float invd = 0.2f / dsum;
        const float* frow = g_f32 + (size_t)(qbase + r) * CDIM;
        float y[8]; float ss = 0.f;
#pragma unroll
        for (int i = 0; i < 8; i++) {
            int col = lane + 32 * i;
            float o = *(float*)(smem + oacc_addr(r, col * 4));
            y[i] = fmaf(0.8f, frow[col], invd * o);
            ss = fmaf(y[i], y[i], ss);
        }
#pragma unroll
        for (int off = 16; off > 0; off >>= 1) ss += __shfl_xor_sync(0xffffffffu, ss, off);
        float inv = 1.0f / fmaxf(sqrtf(ss), 1e-12f);
        float* orow = out + (size_t)(qbase + r) * CDIM;
#pragma unroll
        for (int i = 0; i < 8; i++) orow[lane + 32 * i] = y[i] * inv;
    }
}

// ---------------------------------------------------------------------------
extern "C" void kernel_launch(void* const* d_in, const int* in_sizes, int n_in,
                              void* d_out, int out_size) {
    const float* feats = (const float*)d_in[0];
    float*       out   = (float*)d_out;
    (void)in_sizes; (void)n_in; (void)out_size;

    cudaFuncSetAttribute(attn_kernel,
                         cudaFuncAttributeMaxDynamicSharedMemorySize, SMEM_TOTAL);

    norm_kernel<<<BN / 8, 256>>>(feats);
    attn_kernel<<<BN / MT, NTHREADS, SMEM_TOTAL>>>(out);
}

// round 14
// speedup vs baseline: 1.1970x; 1.0068x over previous
#include <cuda_runtime.h>
#include <cuda_fp16.h>
#include <cstdint>

#define BN 8192
#define CDIM 256
#define MT 64
#define NT 64
#define NTHREADS 384
#define ROWB 512            // smem bytes per K/Q tile row (256 f16)
#define HALF_B 16384        // one 32-key half-tile

#define SQ_OFF 0                      // Q: 64 x 512B = 32KB
#define SK_OFF 32768                  // K: 3 groups x (3 half-slots x 16KB)
#define GSTRIDE 49152
#define SP_OFF 180224                 // P: 3 groups x 8KB (64 x 128B)
#define SMEM_TOTAL 204800
#define OFF_DN 65536                  // epilogue denom overlay (3 x 64 f32)

__device__ float  g_f32[BN * CDIM];   // normalized f (fp32, blend)
__device__ __half g_fh[BN * CDIM];    // normalized f (f16, MMA operand)

// ---------------------------------------------------------------- helpers
__device__ __forceinline__ uint32_t smem_u32(const void* p) {
    uint32_t a;
    asm("{ .reg .u64 t; cvta.to.shared.u64 t, %1; cvt.u32.u64 %0, t; }" : "=r"(a) : "l"(p));
    return a;
}
__device__ __forceinline__ void cp16(uint32_t dst, const void* src) {
    asm volatile("cp.async.cg.shared.global [%0], [%1], 16;" :: "r"(dst), "l"(src));
}
#define CP_COMMIT() asm volatile("cp.async.commit_group;" ::: "memory")

__device__ __forceinline__ void ldsm4(uint32_t a, uint32_t& r0, uint32_t& r1,
                                      uint32_t& r2, uint32_t& r3) {
    asm volatile("ldmatrix.sync.aligned.m8n8.x4.shared.b16 {%0,%1,%2,%3}, [%4];"
                 : "=r"(r0), "=r"(r1), "=r"(r2), "=r"(r3) : "r"(a));
}
__device__ __forceinline__ void ldsm4t(uint32_t a, uint32_t& r0, uint32_t& r1,
                                       uint32_t& r2, uint32_t& r3) {
    asm volatile("ldmatrix.sync.aligned.m8n8.x4.trans.shared.b16 {%0,%1,%2,%3}, [%4];"
                 : "=r"(r0), "=r"(r1), "=r"(r2), "=r"(r3) : "r"(a));
}
__device__ __forceinline__ void mmaH(uint32_t (&c)[2], uint32_t a0, uint32_t a1,
                                     uint32_t a2, uint32_t a3,
                                     uint32_t b0, uint32_t b1) {
    asm volatile("mma.sync.aligned.m16n8k16.row.col.f16.f16.f16.f16 "
                 "{%0,%1}, {%2,%3,%4,%5}, {%6,%7}, {%0,%1};"
                 : "+r"(c[0]), "+r"(c[1])
                 : "r"(a0), "r"(a1), "r"(a2), "r"(a3), "r"(b0), "r"(b1));
}
__device__ __forceinline__ uint32_t exp_h2(uint32_t s) {   // ex2(s*log2e), f16x2
    uint32_t p;
    asm("{ .reg .b32 t;\n\t"
        "mul.rn.f16x2 t, %1, %2;\n\t"
        "ex2.approx.f16x2 %0, t; }"
        : "=r"(p) : "r"(s), "r"(0x3DC53DC5u));
    return p;
}
__device__ __forceinline__ int oacc_addr(int row, int cb) {  // 64x256 f32, 1024B rows
    return row * 1024 + ((((cb >> 4) ^ (row & 7)) << 4) | (cb & 15));
}

// ---------------------------------------------------------------------------
// Kernel 1: row L2-normalize
// ---------------------------------------------------------------------------
__global__ void __launch_bounds__(256) norm_kernel(const float* __restrict__ in) {
    int row  = blockIdx.x * 8 + (threadIdx.x >> 5);
    int lane = threadIdx.x & 31;
    const float* r = in + (size_t)row * CDIM;
    float v[8]; float ss = 0.f;
#pragma unroll
    for (int i = 0; i < 8; i++) { v[i] = r[lane + 32 * i]; ss = fmaf(v[i], v[i], ss); }
#pragma unroll
    for (int o = 16; o > 0; o >>= 1) ss += __shfl_xor_sync(0xffffffffu, ss, o);
    float inv = 1.0f / fmaxf(sqrtf(ss), 1e-12f);
    float*  o32 = g_f32 + (size_t)row * CDIM;
    __half* ofh = g_fh  + (size_t)row * CDIM;
#pragma unroll
    for (int i = 0; i < 8; i++) {
        float x = v[i] * inv;
        o32[lane + 32 * i] = x;
        ofh[lane + 32 * i] = __float2half(x);
    }
}

// Load one 32-key half-tile (16KB) with the group's 128 threads.
__device__ __forceinline__ void load_half(uint32_t dst, int tile, int h, int t128) {
    const __half* src = g_fh + ((size_t)tile * NT + h * 32) * CDIM;
#pragma unroll
    for (int q = 0; q < 8; q++) {
        int i   = t128 + q * 128;
        int row = i >> 5;            // 0..31
        int u   = i & 31;
        cp16(dst + row * ROWB + ((u << 4) ^ ((row & 7) << 4)),
             src + (size_t)row * CDIM + u * 8);
    }
}

// ---------------------------------------------------------------------------
// Kernel 2: 3 decoupled key-groups x 4 warps. S m-split, O n-split via P smem
// exchange (R12), PLUS a 3-slot half-tile ring per group: H1(it+1) prefetched
// mid-O into H0(it)'s slot, H0(it+2) at tile end -> cp.async latency hidden.
// ---------------------------------------------------------------------------
__global__ void __launch_bounds__(NTHREADS, 1) attn_kernel(float* __restrict__ out) {
    extern __shared__ char smem[];
    const uint32_t sb = smem_u32(smem);
    const int tid  = threadIdx.x;
    const int lane = tid & 31;
    const int wid  = tid >> 5;
    const int wm   = wid & 3;      // warp-in-group
    const int gg   = wid >> 2;     // key group 0/1/2
    const int t128 = tid & 127;
    const int g    = lane >> 2;
    const int tg   = lane & 3;
    const int qbase = blockIdx.x * MT;

    const int GBASE = (gg == 0) ? 0 : (gg == 1 ? 43 : 86);
    const int NITER = (gg == 2) ? 42 : 43;
    const uint32_t kbase = sb + SK_OFF + (uint32_t)gg * GSTRIDE;
    const uint32_t pbase = sb + SP_OFF + (uint32_t)gg * 8192u;
    char* const pbytes   = smem + SP_OFF + gg * 8192;

    // prologue: Q (all threads) + T0 halves (commit 0) + T1 half0 (commit 1)
    for (int i = tid; i < 2048; i += NTHREADS) {
        int row = i >> 5, u = i & 31;
        cp16(sb + SQ_OFF + row * ROWB + ((u << 4) ^ ((row & 7) << 4)),
             g_fh + (size_t)(qbase + row) * CDIM + u * 8);
    }
    load_half(kbase,              GBASE,     0, t128);
    load_half(kbase + HALF_B,     GBASE,     1, t128);
    CP_COMMIT();
    load_half(kbase + 2 * HALF_B, GBASE + 1, 0, t128);
    CP_COMMIT();
    asm volatile("cp.async.wait_group 1;" ::: "memory");
    __syncthreads();     // Q + all groups' tile0 visible

    // ldmatrix address components
    const int rowA = wm * 16 + (lane & 15);                 // S-phase A (Q rows)
    const uint32_t aBase = sb + SQ_OFF + rowA * ROWB;
    const int chA = (lane >> 4) << 4, swzA = (rowA & 7) << 4;

    const int rowB0 = (lane & 7) + ((lane >> 4) << 3);      // S-phase B (keys)
    const int chB = ((lane >> 3) & 1) << 4, swzB = (lane & 7) << 4;

    const int rowV0 = (lane & 7) + (((lane >> 3) & 1) << 3); // O-phase B (V, trans)
    const int chV = (lane >> 4) << 4, swzV = (lane & 7) << 4;

    const int rowPA = lane & 15;                             // O-phase A (P tile)
    const uint32_t pldBase = pbase + rowPA * 128;
    const int chP = (lane >> 4) << 4, swzP = (rowPA & 7) << 4;

    uint32_t O[4][8][2];
#pragma unroll
    for (int mb = 0; mb < 4; mb++)
#pragma unroll
        for (int nb = 0; nb < 8; nb++) { O[mb][nb][0] = 0u; O[mb][nb][1] = 0u; }
    float d0 = 0.f, d1 = 0.f;

    int s0 = 0, s1 = 1;   // ring slots of tile(it)'s halves; s2 = 3-s0-s1

#pragma unroll 1
    for (int it = 0; it < NITER; it++) {
        if (it > 0) {
            if (it == NITER - 1) asm volatile("cp.async.wait_group 0;" ::: "memory");
            else                 asm volatile("cp.async.wait_group 1;" ::: "memory");
            asm volatile("bar.sync %0, 128;" :: "r"(gg + 1) : "memory");  // K(it) visible
        }
        const uint32_t h0b = kbase + (uint32_t)s0 * HALF_B;
        const uint32_t h1b = kbase + (uint32_t)s1 * HALF_B;

        // ---- S = Q @ K^T (16 rows x 64 keys per warp, f16 accum) ----
        uint32_t S[8][2];
#pragma unroll
        for (int j = 0; j < 8; j++) { S[j][0] = 0u; S[j][1] = 0u; }
#pragma unroll
        for (int ks = 0; ks < 16; ks++) {
            uint32_t a0, a1, a2, a3;
            ldsm4(aBase + (uint32_t)((chA + 32 * ks) ^ swzA), a0, a1, a2, a3);
#pragma unroll
            for (int j = 0; j < 4; j++) {
                const uint32_t hb = (j < 2) ? h0b : h1b;
                uint32_t b0, b1, b2, b3;
                ldsm4(hb + (rowB0 + 16 * (j & 1)) * ROWB
                         + (uint32_t)((chB + 32 * ks) ^ swzB), b0, b1, b2, b3);
                mmaH(S[2 * j],     a0, a1, a2, a3, b0, b1);
                mmaH(S[2 * j + 1], a0, a1, a2, a3, b2, b3);
            }
        }

        // ---- P = exp(S); denominators; store P slice to group smem tile ----
        {
            __half2 sl = __float2half2_rn(0.f), sh = __float2half2_rn(0.f);
            char* prow = pbytes + (wm * 16 + g) * 128 + 4 * tg;
#pragma unroll
            for (int kb = 0; kb < 4; kb++) {
                uint32_t p0 = exp_h2(S[2 * kb][0]);
                uint32_t p1 = exp_h2(S[2 * kb][1]);
                uint32_t p2 = exp_h2(S[2 * kb + 1][0]);
                uint32_t p3 = exp_h2(S[2 * kb + 1][1]);
                sl = __hadd2(sl, __hadd2(*(__half2*)&p0, *(__half2*)&p2));
                sh = __hadd2(sh, __hadd2(*(__half2*)&p1, *(__half2*)&p3));
                const int u0 = ((2 * kb) ^ g) << 4;
                const int u1 = ((2 * kb + 1) ^ g) << 4;
                *(uint32_t*)(prow + u0)        = p0;
                *(uint32_t*)(prow + 1024 + u0) = p1;
                *(uint32_t*)(prow + u1)        = p2;
                *(uint32_t*)(prow + 1024 + u1) = p3;
            }
            float2 a = __half22float2(sl); d0 += a.x + a.y;
            float2 b = __half22float2(sh); d1 += b.x + b.y;
        }
        asm volatile("bar.sync %0, 128;" :: "r"(gg + 1) : "memory");  // P visible

        // ---- O += P @ V, first half (keys 0-31; V rows in slot s0) ----
#pragma unroll
        for (int ks = 0; ks < 2; ks++) {
            uint32_t pa[4][4];
#pragma unroll
            for (int mb = 0; mb < 4; mb++)
                ldsm4(pldBase + mb * 2048 + (uint32_t)((32 * ks + chP) ^ swzP),
                      pa[mb][0], pa[mb][1], pa[mb][2], pa[mb][3]);
            const uint32_t vrow = h0b + (rowV0 + 16 * ks) * ROWB;
#pragma unroll
            for (int nq = 0; nq < 4; nq++) {
                uint32_t b0, b1, b2, b3;
                ldsm4t(vrow + (uint32_t)((128 * wm + 32 * nq + chV) ^ swzV),
                       b0, b1, b2, b3);
#pragma unroll
                for (int mb = 0; mb < 4; mb++) {
                    mmaH(O[mb][2 * nq],     pa[mb][0], pa[mb][1], pa[mb][2], pa[mb][3], b0, b1);
                    mmaH(O[mb][2 * nq + 1], pa[mb][0], pa[mb][1], pa[mb][2], pa[mb][3], b2, b3);
                }
            }
        }
        // slot s0 (H0(it)) now dead for all 4 warps -> prefetch H1(it+1) into it
        asm volatile("bar.sync %0, 128;" :: "r"(gg + 1) : "memory");
        if (it + 1 < NITER) {
            load_half(kbase + (uint32_t)s0 * HALF_B, GBASE + it + 1, 1, t128);
            CP_COMMIT();
        }

        // ---- O += P @ V, second half (keys 32-63; V rows in slot s1) ----
#pragma unroll
        for (int ks = 2; ks < 4; ks++) {
            uint32_t pa[4][4];
#pragma unroll
            for (int mb = 0; mb < 4; mb++)
                ldsm4(pldBase + mb * 2048 + (uint32_t)((32 * ks + chP) ^ swzP),
                      pa[mb][0], pa[mb][1], pa[mb][2], pa[mb][3]);
            const uint32_t vrow = h1b + (rowV0 + 16 * (ks & 1)) * ROWB;
#pragma unroll
            for (int nq = 0; nq < 4; nq++) {
                uint32_t b0, b1, b2, b3;
                ldsm4t(vrow + (uint32_t)((128 * wm + 32 * nq + chV) ^ swzV),
                       b0, b1, b2, b3);
#pragma unroll
                for (int mb = 0; mb < 4; mb++) {
                    mmaH(O[mb][2 * nq],     pa[mb][0], pa[mb][1], pa[mb][2], pa[mb][3], b0, b1);
                    mmaH(O[mb][2 * nq + 1], pa[mb][0], pa[mb][1], pa[mb][2], pa[mb][3], b2, b3);
                }
            }
        }
        // slot s1 (H1(it)) + P dead -> prefetch H0(it+2) into s1
        asm volatile("bar.sync %0, 128;" :: "r"(gg + 1) : "memory");
        if (it + 2 < NITER) {
            load_half(kbase + (uint32_t)s1 * HALF_B, GBASE + it + 2, 0, t128);
            CP_COMMIT();
        }

        const int s2 = 3 - s0 - s1;   // slot holding H0(it+1)
        s1 = s0; s0 = s2;             // advance ring
    }

    // ---- denominators: quad reduce ----
#pragma unroll
    for (int off = 1; off <= 2; off <<= 1) {
        d0 += __shfl_xor_sync(0xffffffffu, d0, off);
        d1 += __shfl_xor_sync(0xffffffffu, d1, off);
    }

    // ---- epilogue: sum the 3 group O partials into a 64x256 f32 smem tile ----
    __syncthreads();                       // all mainloops done; Q/K/P dead
    float* sDN = (float*)(smem + OFF_DN);
    if (tg == 0) {
        sDN[gg * 64 + wm * 16 + g]     = d0;
        sDN[gg * 64 + wm * 16 + g + 8] = d1;
    }
    if (gg == 0) {
#pragma unroll
        for (int mb = 0; mb < 4; mb++)
#pragma unroll
            for (int nb = 0; nb < 8; nb++) {
                int row = 16 * mb + g;
                int cb  = wm * 256 + nb * 32 + tg * 8;
                *(float2*)(smem + oacc_addr(row, cb))     = __half22float2(*(__half2*)&O[mb][nb][0]);
                *(float2*)(smem + oacc_addr(row + 8, cb)) = __half22float2(*(__half2*)&O[mb][nb][1]);
            }
    }
    __syncthreads();
#pragma unroll 1
    for (int turn = 1; turn <= 2; turn++) {
        if (gg == turn) {
#pragma unroll
            for (int mb = 0; mb < 4; mb++)
#pragma unroll
                for (int nb = 0; nb < 8; nb++) {
                    int row = 16 * mb + g;
                    int cb  = wm * 256 + nb * 32 + tg * 8;
                    float2* a0 = (float2*)(smem + oacc_addr(row, cb));
                    float2* a1 = (float2*)(smem + oacc_addr(row + 8, cb));
                    float2 v0 = __half22float2(*(__half2*)&O[mb][nb][0]);
                    float2 v1 = __half22float2(*(__half2*)&O[mb][nb][1]);
                    float2 c0 = *a0, c1 = *a1;
                    a0->x = c0.x + v0.x; a0->y = c0.y + v0.y;
                    a1->x = c1.x + v1.x; a1->y = c1.y + v1.y;
                }
        }
        __syncthreads();
    }

    // ---- final: blend with f, renormalize rows, write out ----
#pragma unroll 1
    for (int r = wid; r < MT; r += 12) {
        float dsum = sDN[r] + sDN[64 + r] + sDN[128 + r];
        float invd = 0.2f / dsum;
        const float* frow = g_f32 + (size_t)(qbase + r) * CDIM;
        float y[8]; float ss = 0.f;
#pragma unroll
        for (int i = 0; i < 8; i++) {
            int col = lane + 32 * i;
            float o = *(float*)(smem + oacc_addr(r, col * 4));
            y[i] = fmaf(0.8f, frow[col], invd * o);
            ss = fmaf(y[i], y[i], ss);
        }
#pragma unroll
        for (int off = 16; off > 0; off >>= 1) ss += __shfl_xor_sync(0xffffffffu, ss, off);
        float inv = 1.0f / fmaxf(sqrtf(ss), 1e-12f);
        float* orow = out + (size_t)(qbase + r) * CDIM;
#pragma unroll
        for (int i = 0; i < 8; i++) orow[lane + 32 * i] = y[i] * inv;
    }
}

// ---------------------------------------------------------------------------
extern "C" void kernel_launch(void* const* d_in, const int* in_sizes, int n_in,
                              void* d_out, int out_size) {
    const float* feats = (const float*)d_in[0];
    float*       out   = (float*)d_out;
    (void)in_sizes; (void)n_in; (void)out_size;

    cudaFuncSetAttribute(attn_kernel,
                         cudaFuncAttributeMaxDynamicSharedMemorySize, SMEM_TOTAL);

    norm_kernel<<<BN / 8, 256>>>(feats);
    attn_kernel<<<BN / MT, NTHREADS, SMEM_TOTAL>>>(out);
}